// round 2
// baseline (speedup 1.0000x reference)
#include <cuda_runtime.h>
#include <cuda_bf16.h>
#include <stdint.h>

#define NTOK 65536
#define F 256

typedef __nv_bfloat16 bf16;
typedef __nv_bfloat162 bf162;

// ---------------- scratch (device globals; no runtime allocation) ----------------
__device__ __align__(128) bf16 g_XM[(size_t)NTOK * F];       // LN1-mod output, later LN2 output
__device__ __align__(128) bf16 g_QKV[(size_t)NTOK * 3 * F];  // [tok][768] : Q|K|V
__device__ __align__(128) bf16 g_AO[(size_t)NTOK * F];       // attention output
__device__ __align__(128) bf16 g_H[(size_t)NTOK * F];        // silu(LN2X @ W1)
__device__ __align__(128) float g_Ae[256 * F];               // eff LN1 gain = g1*(1+scale)
__device__ __align__(128) float g_Be[256 * F];               // eff LN1 bias = b1*(1+scale)+shift
__device__ __align__(128) bf16 g_Wqkv[F * 3 * F];
__device__ __align__(128) float g_bqkv[3 * F];
__device__ __align__(128) bf16 g_Wo[F * F];
__device__ __align__(128) bf16 g_W1[F * F];
__device__ __align__(128) bf16 g_W2[F * F];
__device__ __align__(128) float g_bias[NTOK];                // attention mask bias (0 / -1e9)

// ---------------- mma / ldmatrix helpers ----------------
__device__ __forceinline__ uint32_t smaddr(const void* p) {
    return (uint32_t)__cvta_generic_to_shared(p);
}
__device__ __forceinline__ void ldm4(uint32_t* r, const void* p) {
    asm volatile("ldmatrix.sync.aligned.m8n8.x4.shared.b16 {%0,%1,%2,%3}, [%4];\n"
                 : "=r"(r[0]), "=r"(r[1]), "=r"(r[2]), "=r"(r[3]) : "r"(smaddr(p)));
}
__device__ __forceinline__ void ldm2(uint32_t* r, const void* p) {
    asm volatile("ldmatrix.sync.aligned.m8n8.x2.shared.b16 {%0,%1}, [%2];\n"
                 : "=r"(r[0]), "=r"(r[1]) : "r"(smaddr(p)));
}
__device__ __forceinline__ void ldm2t(uint32_t* r, const void* p) {
    asm volatile("ldmatrix.sync.aligned.m8n8.x2.trans.shared.b16 {%0,%1}, [%2];\n"
                 : "=r"(r[0]), "=r"(r[1]) : "r"(smaddr(p)));
}
__device__ __forceinline__ void mma16816(float* d, const uint32_t* a, const uint32_t* b) {
    asm volatile("mma.sync.aligned.m16n8k16.row.col.f32.bf16.bf16.f32 "
                 "{%0,%1,%2,%3}, {%4,%5,%6,%7}, {%8,%9}, {%0,%1,%2,%3};\n"
                 : "+f"(d[0]), "+f"(d[1]), "+f"(d[2]), "+f"(d[3])
                 : "r"(a[0]), "r"(a[1]), "r"(a[2]), "r"(a[3]), "r"(b[0]), "r"(b[1]));
}
__device__ __forceinline__ uint32_t packbf(float a, float b) {
    bf162 h = __floats2bfloat162_rn(a, b);
    return *reinterpret_cast<uint32_t*>(&h);
}

// ---------------- prep: modulation table ----------------
__global__ void k_emb(const float* __restrict__ pos, const float* __restrict__ Wemb,
                      const float* __restrict__ bemb, const float* __restrict__ g1,
                      const float* __restrict__ b1) {
    __shared__ float p[F];
    int t = blockIdx.x, c = threadIdx.x;
    p[c] = pos[t * F + c];
    __syncthreads();
    float sh = bemb[c], sc = bemb[F + c];
#pragma unroll 4
    for (int k = 0; k < F; k++) {
        float pv = p[k];
        sh = fmaf(pv, Wemb[k * 512 + c], sh);
        sc = fmaf(pv, Wemb[k * 512 + 256 + c], sc);
    }
    g_Ae[t * F + c] = g1[c] * (1.f + sc);
    g_Be[t * F + c] = b1[c] * (1.f + sc) + sh;
}

// ---------------- prep: weights -> bf16 ----------------
__global__ void k_wcvt(const float* __restrict__ Wq, const float* __restrict__ Wk,
                       const float* __restrict__ Wv, const float* __restrict__ bq,
                       const float* __restrict__ bk, const float* __restrict__ bv,
                       const float* __restrict__ Wo, const float* __restrict__ W1,
                       const float* __restrict__ W2) {
    int i = blockIdx.x * blockDim.x + threadIdx.x;
    int n = i & 255;
    int k = i >> 8;
    g_Wqkv[k * 768 + n]       = __float2bfloat16(Wq[i]);
    g_Wqkv[k * 768 + 256 + n] = __float2bfloat16(Wk[i]);
    g_Wqkv[k * 768 + 512 + n] = __float2bfloat16(Wv[i]);
    g_Wo[i] = __float2bfloat16(Wo[i]);
    g_W1[i] = __float2bfloat16(W1[i]);
    g_W2[i] = __float2bfloat16(W2[i]);
    if (i < F) {
        g_bqkv[i]         = bq[i];
        g_bqkv[F + i]     = bk[i];
        g_bqkv[2 * F + i] = bv[i];
    }
}

// ---------------- mask: bias table + window-AND mask_update ----------------
__global__ void k_maskprep(const void* __restrict__ mask, float* __restrict__ outmask,
                           int write_out) {
    __shared__ int sAll[8];
    int w = blockIdx.x, tid = threadIdx.x;
    uint32_t w0 = *(const uint32_t*)mask;
    int mode = (w0 == 0x01010101u) ? 0 : ((w0 == 0x3F800000u) ? 1 : 2);
    int idx = w * 256 + tid;
    int mv;
    if (mode == 0)      mv = (((const unsigned char*)mask)[idx] != 0);
    else if (mode == 1) mv = (((const float*)mask)[idx] != 0.f);
    else                mv = (((const int*)mask)[idx] != 0);
    g_bias[idx] = mv ? 0.f : -1e9f;
    unsigned bal = __ballot_sync(0xffffffffu, mv);
    if ((tid & 31) == 0) sAll[tid >> 5] = (bal == 0xffffffffu);
    __syncthreads();
    if (write_out) {
        int allv = sAll[0] & sAll[1] & sAll[2] & sAll[3] & sAll[4] & sAll[5] & sAll[6] & sAll[7];
        outmask[idx] = (mv && allv) ? 1.f : 0.f;
    }
}

// ---------------- layernorm (warp per token) -> g_XM bf16 ----------------
__global__ void k_ln(const float* __restrict__ xin, const float* __restrict__ gv,
                     const float* __restrict__ bv, int use_mod) {
    int warp = threadIdx.x >> 5, lane = threadIdx.x & 31;
    int tok = blockIdx.x * 8 + warp;
    const float4* row = (const float4*)(xin + (size_t)tok * F);
    float4 v0 = row[lane], v1 = row[lane + 32];
    float s  = v0.x + v0.y + v0.z + v0.w + v1.x + v1.y + v1.z + v1.w;
    float ss = v0.x * v0.x + v0.y * v0.y + v0.z * v0.z + v0.w * v0.w +
               v1.x * v1.x + v1.y * v1.y + v1.z * v1.z + v1.w * v1.w;
#pragma unroll
    for (int o = 16; o > 0; o >>= 1) {
        s  += __shfl_xor_sync(0xffffffffu, s, o);
        ss += __shfl_xor_sync(0xffffffffu, ss, o);
    }
    float mean = s * (1.f / 256.f);
    float var  = ss * (1.f / 256.f) - mean * mean;
    float r = rsqrtf(var + 1e-5f);
    const float* ap = use_mod ? (g_Ae + (size_t)(tok & 255) * F) : gv;
    const float* bp = use_mod ? (g_Be + (size_t)(tok & 255) * F) : bv;
    const float4* a4 = (const float4*)ap;
    const float4* b4 = (const float4*)bp;
    float4 a0 = a4[lane], a1 = a4[lane + 32];
    float4 b0 = b4[lane], b1 = b4[lane + 32];
    bf162* out = (bf162*)(g_XM + (size_t)tok * F);
    out[lane * 2]      = __floats2bfloat162_rn((v0.x - mean) * r * a0.x + b0.x,
                                               (v0.y - mean) * r * a0.y + b0.y);
    out[lane * 2 + 1]  = __floats2bfloat162_rn((v0.z - mean) * r * a0.z + b0.z,
                                               (v0.w - mean) * r * a0.w + b0.w);
    out[64 + lane * 2]     = __floats2bfloat162_rn((v1.x - mean) * r * a1.x + b1.x,
                                                   (v1.y - mean) * r * a1.y + b1.y);
    out[64 + lane * 2 + 1] = __floats2bfloat162_rn((v1.z - mean) * r * a1.z + b1.z,
                                                   (v1.w - mean) * r * a1.w + b1.w);
}

// ---------------- bf16 tiled GEMM: C[M,N] = A[M,256] @ B[256,N], fused epilogues ----------------
// mode 0: A=g_XM  B=g_Wqkv(ldb768) -> g_QKV = ..+bqkv
// mode 1: A=g_AO  B=g_Wo           -> outf = xres + gam*(..+bo)
// mode 2: A=g_XM  B=g_W1           -> g_H = silu(..)
// mode 3: A=g_H   B=g_W2           -> outf += gam*(..)
__global__ void __launch_bounds__(256) k_gemm(int mode, const float* __restrict__ bias,
                                              const float* __restrict__ xres,
                                              const float* __restrict__ gamv,
                                              float* __restrict__ outf) {
    __shared__ bf16 sA[128][40];
    __shared__ bf16 sB[32][72];
    const bf16* A;
    const bf16* B;
    int ldb;
    if (mode == 0)      { A = g_XM; B = g_Wqkv; ldb = 768; }
    else if (mode == 1) { A = g_AO; B = g_Wo;   ldb = 256; }
    else if (mode == 2) { A = g_XM; B = g_W1;   ldb = 256; }
    else                { A = g_H;  B = g_W2;   ldb = 256; }

    int tid = threadIdx.x;
    int lane = tid & 31, warp = tid >> 5;
    int wm = warp & 3, wn = warp >> 2;
    int bm = blockIdx.y * 128, bn = blockIdx.x * 64;

    float acc[2][4][4];
#pragma unroll
    for (int i = 0; i < 2; i++)
#pragma unroll
        for (int j = 0; j < 4; j++)
#pragma unroll
            for (int q = 0; q < 4; q++) acc[i][j][q] = 0.f;

    int arow = tid >> 1, aseg = tid & 1;
    int brow = tid >> 3, bc8 = tid & 7;

    for (int k0 = 0; k0 < 256; k0 += 32) {
        const uint4* asrc = (const uint4*)(A + (size_t)(bm + arow) * 256 + k0 + aseg * 16);
        uint4 av0 = asrc[0], av1 = asrc[1];
        const uint4* bsrc = (const uint4*)(B + (size_t)(k0 + brow) * ldb + bn + bc8 * 8);
        uint4 bvv = bsrc[0];
        __syncthreads();
        *(uint4*)&sA[arow][aseg * 16]     = av0;
        *(uint4*)&sA[arow][aseg * 16 + 8] = av1;
        *(uint4*)&sB[brow][bc8 * 8]       = bvv;
        __syncthreads();
#pragma unroll
        for (int kk = 0; kk < 32; kk += 16) {
            uint32_t af[2][4];
#pragma unroll
            for (int mt = 0; mt < 2; mt++)
                ldm4(af[mt], &sA[wm * 32 + mt * 16 + (lane & 15)][kk + (lane >> 4) * 8]);
            uint32_t bfr[4][2];
#pragma unroll
            for (int nt = 0; nt < 4; nt++)
                ldm2t(bfr[nt], &sB[kk + (lane & 15)][wn * 32 + nt * 8]);
#pragma unroll
            for (int mt = 0; mt < 2; mt++)
#pragma unroll
                for (int nt = 0; nt < 4; nt++)
                    mma16816(acc[mt][nt], af[mt], bfr[nt]);
        }
    }

#pragma unroll
    for (int mt = 0; mt < 2; mt++) {
        int r0 = bm + wm * 32 + mt * 16 + (lane >> 2);
#pragma unroll
        for (int nt = 0; nt < 4; nt++) {
            int cb = bn + wn * 32 + nt * 8 + (lane & 3) * 2;
            float c0 = acc[mt][nt][0], c1 = acc[mt][nt][1];
            float c2 = acc[mt][nt][2], c3 = acc[mt][nt][3];
            if (mode == 0) {
                float b0 = g_bqkv[cb], b1 = g_bqkv[cb + 1];
                *(bf162*)&g_QKV[(size_t)r0 * 768 + cb]       = __floats2bfloat162_rn(c0 + b0, c1 + b1);
                *(bf162*)&g_QKV[(size_t)(r0 + 8) * 768 + cb] = __floats2bfloat162_rn(c2 + b0, c3 + b1);
            } else if (mode == 1) {
                float b0 = bias[cb], b1 = bias[cb + 1];
                float gm0 = gamv[cb], gm1 = gamv[cb + 1];
                size_t i0 = (size_t)r0 * 256 + cb, i1 = (size_t)(r0 + 8) * 256 + cb;
                float2 o0, o1;
                o0.x = xres[i0]     + gm0 * (c0 + b0);
                o0.y = xres[i0 + 1] + gm1 * (c1 + b1);
                o1.x = xres[i1]     + gm0 * (c2 + b0);
                o1.y = xres[i1 + 1] + gm1 * (c3 + b1);
                *(float2*)&outf[i0] = o0;
                *(float2*)&outf[i1] = o1;
            } else if (mode == 2) {
                float s0 = c0 / (1.f + expf(-c0));
                float s1 = c1 / (1.f + expf(-c1));
                float s2 = c2 / (1.f + expf(-c2));
                float s3 = c3 / (1.f + expf(-c3));
                *(bf162*)&g_H[(size_t)r0 * 256 + cb]       = __floats2bfloat162_rn(s0, s1);
                *(bf162*)&g_H[(size_t)(r0 + 8) * 256 + cb] = __floats2bfloat162_rn(s2, s3);
            } else {
                float gm0 = gamv[cb], gm1 = gamv[cb + 1];
                size_t i0 = (size_t)r0 * 256 + cb, i1 = (size_t)(r0 + 8) * 256 + cb;
                outf[i0]     += gm0 * c0;
                outf[i0 + 1] += gm1 * c1;
                outf[i1]     += gm0 * c2;
                outf[i1 + 1] += gm1 * c3;
            }
        }
    }
}

// ---------------- attention: CTA per (window, head); warp = 32 query rows; online softmax ----------------
__global__ void __launch_bounds__(256) k_attn() {
    __shared__ bf16 smK[256][40];
    __shared__ bf16 smV[256][40];
    __shared__ float sBias[256];
    int w = blockIdx.x, h = blockIdx.y;
    int tid = threadIdx.x, warp = tid >> 5, lane = tid & 31;
    const bf16* base = g_QKV + (size_t)w * 256 * 768 + h * 32;

    {
        const uint4* ks = (const uint4*)(base + (size_t)tid * 768 + 256);
        const uint4* vs = (const uint4*)(base + (size_t)tid * 768 + 512);
        uint4 k0 = ks[0], k1 = ks[1], k2 = ks[2], k3 = ks[3];
        uint4 v0 = vs[0], v1 = vs[1], v2 = vs[2], v3 = vs[3];
        uint4* kd = (uint4*)&smK[tid][0];
        kd[0] = k0; kd[1] = k1; kd[2] = k2; kd[3] = k3;
        uint4* vd = (uint4*)&smV[tid][0];
        vd[0] = v0; vd[1] = v1; vd[2] = v2; vd[3] = v3;
        sBias[tid] = g_bias[w * 256 + tid];
    }

    // Q fragments loaded directly from global (A-frag layout)
    uint32_t qf[2][2][4];
    int qr = lane >> 2, qc = (lane & 3) * 2;
#pragma unroll
    for (int mt = 0; mt < 2; mt++)
#pragma unroll
        for (int kt = 0; kt < 2; kt++) {
            const bf16* qp = base + (size_t)(warp * 32 + mt * 16) * 768;
            qf[mt][kt][0] = *(const uint32_t*)(qp + (size_t)qr * 768 + kt * 16 + qc);
            qf[mt][kt][1] = *(const uint32_t*)(qp + (size_t)(qr + 8) * 768 + kt * 16 + qc);
            qf[mt][kt][2] = *(const uint32_t*)(qp + (size_t)qr * 768 + kt * 16 + qc + 8);
            qf[mt][kt][3] = *(const uint32_t*)(qp + (size_t)(qr + 8) * 768 + kt * 16 + qc + 8);
        }
    __syncthreads();

    float O[2][4][4];
    float mrow[2][2], lrow[2][2];
#pragma unroll
    for (int mt = 0; mt < 2; mt++) {
        mrow[mt][0] = -1e30f; mrow[mt][1] = -1e30f;
        lrow[mt][0] = 0.f;    lrow[mt][1] = 0.f;
#pragma unroll
        for (int d = 0; d < 4; d++)
#pragma unroll
            for (int q = 0; q < 4; q++) O[mt][d][q] = 0.f;
    }
    const float sc = 0.17677669529663687f;  // 1/sqrt(32)

    for (int c = 0; c < 4; c++) {
        float s[2][8][4];
#pragma unroll
        for (int mt = 0; mt < 2; mt++)
#pragma unroll
            for (int nt = 0; nt < 8; nt++)
#pragma unroll
                for (int q = 0; q < 4; q++) s[mt][nt][q] = 0.f;
        // S = Q K^T
#pragma unroll
        for (int nt = 0; nt < 8; nt++) {
            int key0 = c * 64 + nt * 8;
#pragma unroll
            for (int kt = 0; kt < 2; kt++) {
                uint32_t kb[2];
                ldm2(kb, &smK[key0 + (lane & 7)][kt * 16 + ((lane >> 3) & 1) * 8]);
                mma16816(s[0][nt], qf[0][kt], kb);
                mma16816(s[1][nt], qf[1][kt], kb);
            }
        }
        // scale + mask bias
#pragma unroll
        for (int nt = 0; nt < 8; nt++) {
            int kcol = c * 64 + nt * 8 + qc;
            float b0 = sBias[kcol], b1 = sBias[kcol + 1];
#pragma unroll
            for (int mt = 0; mt < 2; mt++) {
                s[mt][nt][0] = s[mt][nt][0] * sc + b0;
                s[mt][nt][1] = s[mt][nt][1] * sc + b1;
                s[mt][nt][2] = s[mt][nt][2] * sc + b0;
                s[mt][nt][3] = s[mt][nt][3] * sc + b1;
            }
        }
        // online softmax update
#pragma unroll
        for (int mt = 0; mt < 2; mt++) {
            float rm0 = -1e30f, rm1 = -1e30f;
#pragma unroll
            for (int nt = 0; nt < 8; nt++) {
                rm0 = fmaxf(rm0, fmaxf(s[mt][nt][0], s[mt][nt][1]));
                rm1 = fmaxf(rm1, fmaxf(s[mt][nt][2], s[mt][nt][3]));
            }
#pragma unroll
            for (int o = 1; o <= 2; o <<= 1) {
                rm0 = fmaxf(rm0, __shfl_xor_sync(0xffffffffu, rm0, o));
                rm1 = fmaxf(rm1, __shfl_xor_sync(0xffffffffu, rm1, o));
            }
            float mn0 = fmaxf(mrow[mt][0], rm0), mn1 = fmaxf(mrow[mt][1], rm1);
            float sc0 = expf(mrow[mt][0] - mn0), sc1 = expf(mrow[mt][1] - mn1);
            mrow[mt][0] = mn0; mrow[mt][1] = mn1;
            float rs0 = 0.f, rs1 = 0.f;
#pragma unroll
            for (int nt = 0; nt < 8; nt++) {
                s[mt][nt][0] = expf(s[mt][nt][0] - mn0);
                s[mt][nt][1] = expf(s[mt][nt][1] - mn0);
                s[mt][nt][2] = expf(s[mt][nt][2] - mn1);
                s[mt][nt][3] = expf(s[mt][nt][3] - mn1);
                rs0 += s[mt][nt][0] + s[mt][nt][1];
                rs1 += s[mt][nt][2] + s[mt][nt][3];
            }
#pragma unroll
            for (int o = 1; o <= 2; o <<= 1) {
                rs0 += __shfl_xor_sync(0xffffffffu, rs0, o);
                rs1 += __shfl_xor_sync(0xffffffffu, rs1, o);
            }
            lrow[mt][0] = lrow[mt][0] * sc0 + rs0;
            lrow[mt][1] = lrow[mt][1] * sc1 + rs1;
#pragma unroll
            for (int d = 0; d < 4; d++) {
                O[mt][d][0] *= sc0; O[mt][d][1] *= sc0;
                O[mt][d][2] *= sc1; O[mt][d][3] *= sc1;
            }
        }
        // O += P V
#pragma unroll
        for (int kt2 = 0; kt2 < 4; kt2++) {
            uint32_t pa[2][4];
#pragma unroll
            for (int mt = 0; mt < 2; mt++) {
                pa[mt][0] = packbf(s[mt][2 * kt2][0],     s[mt][2 * kt2][1]);
                pa[mt][1] = packbf(s[mt][2 * kt2][2],     s[mt][2 * kt2][3]);
                pa[mt][2] = packbf(s[mt][2 * kt2 + 1][0], s[mt][2 * kt2 + 1][1]);
                pa[mt][3] = packbf(s[mt][2 * kt2 + 1][2], s[mt][2 * kt2 + 1][3]);
            }
#pragma unroll
            for (int d = 0; d < 4; d++) {
                uint32_t vb[2];
                ldm2t(vb, &smV[c * 64 + kt2 * 16 + (lane & 15)][d * 8]);
                mma16816(O[0][d], pa[0], vb);
                mma16816(O[1][d], pa[1], vb);
            }
        }
    }

    // epilogue
#pragma unroll
    for (int mt = 0; mt < 2; mt++) {
        float il0 = 1.f / lrow[mt][0], il1 = 1.f / lrow[mt][1];
        int r0 = w * 256 + warp * 32 + mt * 16 + qr;
#pragma unroll
        for (int d = 0; d < 4; d++) {
            int col = h * 32 + d * 8 + qc;
            *(bf162*)&g_AO[(size_t)r0 * 256 + col] =
                __floats2bfloat162_rn(O[mt][d][0] * il0, O[mt][d][1] * il0);
            *(bf162*)&g_AO[(size_t)(r0 + 8) * 256 + col] =
                __floats2bfloat162_rn(O[mt][d][2] * il1, O[mt][d][3] * il1);
        }
    }
}

// ---------------- launch ----------------
extern "C" void kernel_launch(void* const* d_in, const int* in_sizes, int n_in,
                              void* d_out, int out_size) {
    const float* x    = (const float*)d_in[0];
    const void*  mask = d_in[1];
    const float* pos  = (const float*)d_in[2];
    const float* Wemb = (const float*)d_in[3];
    const float* bemb = (const float*)d_in[4];
    const float* g1   = (const float*)d_in[5];
    const float* b1   = (const float*)d_in[6];
    const float* Wq   = (const float*)d_in[7];
    const float* bq   = (const float*)d_in[8];
    const float* Wk   = (const float*)d_in[9];
    const float* bk   = (const float*)d_in[10];
    const float* Wv   = (const float*)d_in[11];
    const float* bv   = (const float*)d_in[12];
    const float* Wo   = (const float*)d_in[13];
    const float* bo   = (const float*)d_in[14];
    const float* g2   = (const float*)d_in[15];
    const float* b2   = (const float*)d_in[16];
    const float* W1   = (const float*)d_in[17];
    const float* W2   = (const float*)d_in[18];
    const float* gam  = (const float*)d_in[19];
    const float* gmlp = (const float*)d_in[20];
    (void)in_sizes; (void)n_in;

    float* outx = (float*)d_out;
    int write_mask = (out_size >= 16777216 + 65536) ? 1 : 0;
    float* outmask = outx + 16777216;

    k_emb<<<256, 256>>>(pos, Wemb, bemb, g1, b1);
    k_wcvt<<<256, 256>>>(Wq, Wk, Wv, bq, bk, bv, Wo, W1, W2);
    k_maskprep<<<256, 256>>>(mask, outmask, write_mask);
    k_ln<<<8192, 256>>>(x, g1, b1, 1);
    dim3 gq(12, 512);
    k_gemm<<<gq, 256>>>(0, nullptr, nullptr, nullptr, nullptr);
    dim3 ga(256, 8);
    k_attn<<<ga, 256>>>();
    dim3 g4(4, 512);
    k_gemm<<<g4, 256>>>(1, bo, x, gam, outx);
    k_ln<<<8192, 256>>>(outx, g2, b2, 0);
    k_gemm<<<g4, 256>>>(2, nullptr, nullptr, nullptr, nullptr);
    k_gemm<<<g4, 256>>>(3, nullptr, nullptr, gmlp, outx);
}

// round 4
// speedup vs baseline: 1.3617x; 1.3617x over previous
#include <cuda_runtime.h>
#include <cuda_bf16.h>
#include <stdint.h>

#define NTOK 65536
#define F 256

typedef __nv_bfloat16 bf16;
typedef __nv_bfloat162 bf162;

// ---------------- scratch ----------------
__device__ __align__(128) bf16 g_XM[(size_t)NTOK * F];
__device__ __align__(128) bf16 g_QKV[(size_t)NTOK * 3 * F];
__device__ __align__(128) bf16 g_AO[(size_t)NTOK * F];
__device__ __align__(128) bf16 g_H[(size_t)NTOK * F];
__device__ __align__(128) float g_Ae[256 * F];
__device__ __align__(128) float g_Be[256 * F];
__device__ __align__(128) bf16 g_Wqkv[F * 3 * F];
__device__ __align__(128) float g_bqkv[3 * F];
__device__ __align__(128) bf16 g_Wo[F * F];
__device__ __align__(128) bf16 g_W1[F * F];
__device__ __align__(128) bf16 g_W2[F * F];
__device__ __align__(128) float g_bias[NTOK];

// ---------------- helpers ----------------
__device__ __forceinline__ uint32_t smaddr(const void* p) {
    return (uint32_t)__cvta_generic_to_shared(p);
}
__device__ __forceinline__ void cpasync16(uint32_t dst, const void* src) {
    asm volatile("cp.async.cg.shared.global [%0], [%1], 16;\n" :: "r"(dst), "l"(src));
}
__device__ __forceinline__ void cpcommit() {
    asm volatile("cp.async.commit_group;\n");
}
__device__ __forceinline__ void ldm4(uint32_t* r, const void* p) {
    asm volatile("ldmatrix.sync.aligned.m8n8.x4.shared.b16 {%0,%1,%2,%3}, [%4];\n"
                 : "=r"(r[0]), "=r"(r[1]), "=r"(r[2]), "=r"(r[3]) : "r"(smaddr(p)));
}
__device__ __forceinline__ void ldm4t(uint32_t* r, const void* p) {
    asm volatile("ldmatrix.sync.aligned.m8n8.x4.trans.shared.b16 {%0,%1,%2,%3}, [%4];\n"
                 : "=r"(r[0]), "=r"(r[1]), "=r"(r[2]), "=r"(r[3]) : "r"(smaddr(p)));
}
__device__ __forceinline__ void ldm2(uint32_t* r, const void* p) {
    asm volatile("ldmatrix.sync.aligned.m8n8.x2.shared.b16 {%0,%1}, [%2];\n"
                 : "=r"(r[0]), "=r"(r[1]) : "r"(smaddr(p)));
}
__device__ __forceinline__ void ldm2t(uint32_t* r, const void* p) {
    asm volatile("ldmatrix.sync.aligned.m8n8.x2.trans.shared.b16 {%0,%1}, [%2];\n"
                 : "=r"(r[0]), "=r"(r[1]) : "r"(smaddr(p)));
}
__device__ __forceinline__ void mma16816(float* d, const uint32_t* a, const uint32_t* b) {
    asm volatile("mma.sync.aligned.m16n8k16.row.col.f32.bf16.bf16.f32 "
                 "{%0,%1,%2,%3}, {%4,%5,%6,%7}, {%8,%9}, {%0,%1,%2,%3};\n"
                 : "+f"(d[0]), "+f"(d[1]), "+f"(d[2]), "+f"(d[3])
                 : "r"(a[0]), "r"(a[1]), "r"(a[2]), "r"(a[3]), "r"(b[0]), "r"(b[1]));
}
__device__ __forceinline__ uint32_t packbf(float a, float b) {
    bf162 h = __floats2bfloat162_rn(a, b);
    return *reinterpret_cast<uint32_t*>(&h);
}

// ---------------- prep: modulation table ----------------
__global__ void k_emb(const float* __restrict__ pos, const float* __restrict__ Wemb,
                      const float* __restrict__ bemb, const float* __restrict__ g1,
                      const float* __restrict__ b1) {
    __shared__ float p[F];
    int t = blockIdx.x, c = threadIdx.x;
    p[c] = pos[t * F + c];
    __syncthreads();
    float sh = bemb[c], sc = bemb[F + c];
#pragma unroll 4
    for (int k = 0; k < F; k++) {
        float pv = p[k];
        sh = fmaf(pv, Wemb[k * 512 + c], sh);
        sc = fmaf(pv, Wemb[k * 512 + 256 + c], sc);
    }
    g_Ae[t * F + c] = g1[c] * (1.f + sc);
    g_Be[t * F + c] = b1[c] * (1.f + sc) + sh;
}

// ---------------- prep: weights -> bf16 ----------------
__global__ void k_wcvt(const float* __restrict__ Wq, const float* __restrict__ Wk,
                       const float* __restrict__ Wv, const float* __restrict__ bq,
                       const float* __restrict__ bk, const float* __restrict__ bv,
                       const float* __restrict__ Wo, const float* __restrict__ W1,
                       const float* __restrict__ W2) {
    int i = blockIdx.x * blockDim.x + threadIdx.x;
    int n = i & 255;
    int k = i >> 8;
    g_Wqkv[k * 768 + n]       = __float2bfloat16(Wq[i]);
    g_Wqkv[k * 768 + 256 + n] = __float2bfloat16(Wk[i]);
    g_Wqkv[k * 768 + 512 + n] = __float2bfloat16(Wv[i]);
    g_Wo[i] = __float2bfloat16(Wo[i]);
    g_W1[i] = __float2bfloat16(W1[i]);
    g_W2[i] = __float2bfloat16(W2[i]);
    if (i < F) {
        g_bqkv[i]         = bq[i];
        g_bqkv[F + i]     = bk[i];
        g_bqkv[2 * F + i] = bv[i];
    }
}

// ---------------- mask prep ----------------
__global__ void k_maskprep(const void* __restrict__ mask, float* __restrict__ outmask,
                           int write_out) {
    __shared__ int sAll[8];
    int w = blockIdx.x, tid = threadIdx.x;
    uint32_t w0 = *(const uint32_t*)mask;
    int mode = (w0 == 0x01010101u) ? 0 : ((w0 == 0x3F800000u) ? 1 : 2);
    int idx = w * 256 + tid;
    int mv;
    if (mode == 0)      mv = (((const unsigned char*)mask)[idx] != 0);
    else if (mode == 1) mv = (((const float*)mask)[idx] != 0.f);
    else                mv = (((const int*)mask)[idx] != 0);
    g_bias[idx] = mv ? 0.f : -1e9f;
    unsigned bal = __ballot_sync(0xffffffffu, mv);
    if ((tid & 31) == 0) sAll[tid >> 5] = (bal == 0xffffffffu);
    __syncthreads();
    if (write_out) {
        int allv = sAll[0] & sAll[1] & sAll[2] & sAll[3] & sAll[4] & sAll[5] & sAll[6] & sAll[7];
        outmask[idx] = (mv && allv) ? 1.f : 0.f;
    }
}

// ---------------- layernorm ----------------
__global__ void k_ln(const float* __restrict__ xin, const float* __restrict__ gv,
                     const float* __restrict__ bv, int use_mod) {
    int warp = threadIdx.x >> 5, lane = threadIdx.x & 31;
    int tok = blockIdx.x * 8 + warp;
    const float4* row = (const float4*)(xin + (size_t)tok * F);
    float4 v0 = row[lane], v1 = row[lane + 32];
    float s  = v0.x + v0.y + v0.z + v0.w + v1.x + v1.y + v1.z + v1.w;
    float ss = v0.x * v0.x + v0.y * v0.y + v0.z * v0.z + v0.w * v0.w +
               v1.x * v1.x + v1.y * v1.y + v1.z * v1.z + v1.w * v1.w;
#pragma unroll
    for (int o = 16; o > 0; o >>= 1) {
        s  += __shfl_xor_sync(0xffffffffu, s, o);
        ss += __shfl_xor_sync(0xffffffffu, ss, o);
    }
    float mean = s * (1.f / 256.f);
    float var  = ss * (1.f / 256.f) - mean * mean;
    float r = rsqrtf(var + 1e-5f);
    const float* ap = use_mod ? (g_Ae + (size_t)(tok & 255) * F) : gv;
    const float* bp = use_mod ? (g_Be + (size_t)(tok & 255) * F) : bv;
    const float4* a4 = (const float4*)ap;
    const float4* b4 = (const float4*)bp;
    float4 a0 = a4[lane], a1 = a4[lane + 32];
    float4 b0 = b4[lane], b1 = b4[lane + 32];
    bf162* out = (bf162*)(g_XM + (size_t)tok * F);
    out[lane * 2]      = __floats2bfloat162_rn((v0.x - mean) * r * a0.x + b0.x,
                                               (v0.y - mean) * r * a0.y + b0.y);
    out[lane * 2 + 1]  = __floats2bfloat162_rn((v0.z - mean) * r * a0.z + b0.z,
                                               (v0.w - mean) * r * a0.w + b0.w);
    out[64 + lane * 2]     = __floats2bfloat162_rn((v1.x - mean) * r * a1.x + b1.x,
                                                   (v1.y - mean) * r * a1.y + b1.y);
    out[64 + lane * 2 + 1] = __floats2bfloat162_rn((v1.z - mean) * r * a1.z + b1.z,
                                                   (v1.w - mean) * r * a1.w + b1.w);
}

// ---------------- GEMM: C[M,N] = A[M,256] @ B[256,N], 128x128x32 tiles, cp.async 2-stage ----------------
// mode 0: A=g_XM  B=g_Wqkv(ldb768) -> g_QKV = ..+bqkv
// mode 1: A=g_AO  B=g_Wo           -> outf = xres + gam*(..+bo)
// mode 2: A=g_XM  B=g_W1           -> g_H = silu(..)
// mode 3: A=g_H   B=g_W2           -> outf += gam*(..)
__global__ void __launch_bounds__(256, 2) k_gemm(int mode, const float* __restrict__ bias,
                                                 const float* __restrict__ xres,
                                                 const float* __restrict__ gamv,
                                                 float* __restrict__ outf) {
    __shared__ bf16 sA[2][128][40];
    __shared__ bf16 sB[2][32][136];
    const bf16* A;
    const bf16* B;
    int ldb;
    if (mode == 0)      { A = g_XM; B = g_Wqkv; ldb = 768; }
    else if (mode == 1) { A = g_AO; B = g_Wo;   ldb = 256; }
    else if (mode == 2) { A = g_XM; B = g_W1;   ldb = 256; }
    else                { A = g_H;  B = g_W2;   ldb = 256; }

    int tid = threadIdx.x;
    int lane = tid & 31, warp = tid >> 5;
    int wm = warp & 1, wn = warp >> 1;            // warp tile: 64 (m) x 32 (n)
    int bm = blockIdx.y * 128, bn = blockIdx.x * 128;

    float acc[4][4][4];
#pragma unroll
    for (int i = 0; i < 4; i++)
#pragma unroll
        for (int j = 0; j < 4; j++)
#pragma unroll
            for (int q = 0; q < 4; q++) acc[i][j][q] = 0.f;

    int arow = tid >> 1, aseg = tid & 1;          // A: 128 rows, 2x16B per row-half
    int brow = tid >> 3, bc16 = tid & 7;          // B: 32 rows, 8x(16 elems) per row

    const bf16* asrc0 = A + (size_t)(bm + arow) * 256 + aseg * 16;
    const bf16* bsrc0 = B + (size_t)brow * ldb + bn + bc16 * 16;

#define PREFETCH(st, k0)                                                      \
    do {                                                                      \
        uint32_t ad = smaddr(&sA[st][arow][aseg * 16]);                       \
        cpasync16(ad, asrc0 + (k0));                                          \
        cpasync16(ad + 16, asrc0 + (k0) + 8);                                 \
        uint32_t bd = smaddr(&sB[st][brow][bc16 * 16]);                       \
        cpasync16(bd, bsrc0 + (size_t)(k0) * ldb);                            \
        cpasync16(bd + 16, bsrc0 + (size_t)(k0) * ldb + 8);                   \
        cpcommit();                                                           \
    } while (0)

    PREFETCH(0, 0);
#pragma unroll
    for (int ks = 0; ks < 8; ks++) {
        int st = ks & 1;
        if (ks < 7) PREFETCH(st ^ 1, (ks + 1) * 32);
        if (ks < 7) asm volatile("cp.async.wait_group 1;\n");
        else        asm volatile("cp.async.wait_group 0;\n");
        __syncthreads();
#pragma unroll
        for (int kk = 0; kk < 32; kk += 16) {
            uint32_t af[4][4];
#pragma unroll
            for (int mt = 0; mt < 4; mt++)
                ldm4(af[mt], &sA[st][wm * 64 + mt * 16 + (lane & 15)][kk + (lane >> 4) * 8]);
            uint32_t bfr[2][4];
#pragma unroll
            for (int nb = 0; nb < 2; nb++)
                ldm4t(bfr[nb], &sB[st][kk + (lane & 15)][wn * 32 + nb * 16 + (lane >> 4) * 8]);
#pragma unroll
            for (int mt = 0; mt < 4; mt++)
#pragma unroll
                for (int nt = 0; nt < 4; nt++)
                    mma16816(acc[mt][nt], af[mt], &bfr[nt >> 1][(nt & 1) * 2]);
        }
        __syncthreads();
    }
#undef PREFETCH

#pragma unroll
    for (int mt = 0; mt < 4; mt++) {
        int r0 = bm + wm * 64 + mt * 16 + (lane >> 2);
#pragma unroll
        for (int nt = 0; nt < 4; nt++) {
            int cb = bn + wn * 32 + nt * 8 + (lane & 3) * 2;
            float c0 = acc[mt][nt][0], c1 = acc[mt][nt][1];
            float c2 = acc[mt][nt][2], c3 = acc[mt][nt][3];
            if (mode == 0) {
                float b0 = g_bqkv[cb], b1 = g_bqkv[cb + 1];
                *(bf162*)&g_QKV[(size_t)r0 * 768 + cb]       = __floats2bfloat162_rn(c0 + b0, c1 + b1);
                *(bf162*)&g_QKV[(size_t)(r0 + 8) * 768 + cb] = __floats2bfloat162_rn(c2 + b0, c3 + b1);
            } else if (mode == 1) {
                float b0 = bias[cb], b1 = bias[cb + 1];
                float gm0 = gamv[cb], gm1 = gamv[cb + 1];
                size_t i0 = (size_t)r0 * 256 + cb, i1 = (size_t)(r0 + 8) * 256 + cb;
                float2 o0, o1;
                o0.x = xres[i0]     + gm0 * (c0 + b0);
                o0.y = xres[i0 + 1] + gm1 * (c1 + b1);
                o1.x = xres[i1]     + gm0 * (c2 + b0);
                o1.y = xres[i1 + 1] + gm1 * (c3 + b1);
                *(float2*)&outf[i0] = o0;
                *(float2*)&outf[i1] = o1;
            } else if (mode == 2) {
                float s0 = c0 / (1.f + __expf(-c0));
                float s1 = c1 / (1.f + __expf(-c1));
                float s2 = c2 / (1.f + __expf(-c2));
                float s3 = c3 / (1.f + __expf(-c3));
                *(bf162*)&g_H[(size_t)r0 * 256 + cb]       = __floats2bfloat162_rn(s0, s1);
                *(bf162*)&g_H[(size_t)(r0 + 8) * 256 + cb] = __floats2bfloat162_rn(s2, s3);
            } else {
                float gm0 = gamv[cb], gm1 = gamv[cb + 1];
                size_t i0 = (size_t)r0 * 256 + cb, i1 = (size_t)(r0 + 8) * 256 + cb;
                outf[i0]     += gm0 * c0;
                outf[i0 + 1] += gm1 * c1;
                outf[i1]     += gm0 * c2;
                outf[i1 + 1] += gm1 * c3;
            }
        }
    }
}

// ---------------- attention (mma.sync, __expf) ----------------
__global__ void __launch_bounds__(256) k_attn() {
    __shared__ bf16 smK[256][40];
    __shared__ bf16 smV[256][40];
    __shared__ float sBias[256];
    int w = blockIdx.x, h = blockIdx.y;
    int tid = threadIdx.x, warp = tid >> 5, lane = tid & 31;
    const bf16* base = g_QKV + (size_t)w * 256 * 768 + h * 32;

    {
        const uint4* ks = (const uint4*)(base + (size_t)tid * 768 + 256);
        const uint4* vs = (const uint4*)(base + (size_t)tid * 768 + 512);
        uint4 k0 = ks[0], k1 = ks[1], k2 = ks[2], k3 = ks[3];
        uint4 v0 = vs[0], v1 = vs[1], v2 = vs[2], v3 = vs[3];
        uint4* kd = (uint4*)&smK[tid][0];
        kd[0] = k0; kd[1] = k1; kd[2] = k2; kd[3] = k3;
        uint4* vd = (uint4*)&smV[tid][0];
        vd[0] = v0; vd[1] = v1; vd[2] = v2; vd[3] = v3;
        sBias[tid] = g_bias[w * 256 + tid];
    }

    uint32_t qf[2][2][4];
    int qr = lane >> 2, qc = (lane & 3) * 2;
#pragma unroll
    for (int mt = 0; mt < 2; mt++)
#pragma unroll
        for (int kt = 0; kt < 2; kt++) {
            const bf16* qp = base + (size_t)(warp * 32 + mt * 16) * 768;
            qf[mt][kt][0] = *(const uint32_t*)(qp + (size_t)qr * 768 + kt * 16 + qc);
            qf[mt][kt][1] = *(const uint32_t*)(qp + (size_t)(qr + 8) * 768 + kt * 16 + qc);
            qf[mt][kt][2] = *(const uint32_t*)(qp + (size_t)qr * 768 + kt * 16 + qc + 8);
            qf[mt][kt][3] = *(const uint32_t*)(qp + (size_t)(qr + 8) * 768 + kt * 16 + qc + 8);
        }
    __syncthreads();

    float O[2][4][4];
    float mrow[2][2], lrow[2][2];
#pragma unroll
    for (int mt = 0; mt < 2; mt++) {
        mrow[mt][0] = -1e30f; mrow[mt][1] = -1e30f;
        lrow[mt][0] = 0.f;    lrow[mt][1] = 0.f;
#pragma unroll
        for (int d = 0; d < 4; d++)
#pragma unroll
            for (int q = 0; q < 4; q++) O[mt][d][q] = 0.f;
    }
    const float sc = 0.17677669529663687f;

    for (int c = 0; c < 4; c++) {
        float s[2][8][4];
#pragma unroll
        for (int mt = 0; mt < 2; mt++)
#pragma unroll
            for (int nt = 0; nt < 8; nt++)
#pragma unroll
                for (int q = 0; q < 4; q++) s[mt][nt][q] = 0.f;
#pragma unroll
        for (int nt = 0; nt < 8; nt++) {
            int key0 = c * 64 + nt * 8;
#pragma unroll
            for (int kt = 0; kt < 2; kt++) {
                uint32_t kb[2];
                ldm2(kb, &smK[key0 + (lane & 7)][kt * 16 + ((lane >> 3) & 1) * 8]);
                mma16816(s[0][nt], qf[0][kt], kb);
                mma16816(s[1][nt], qf[1][kt], kb);
            }
        }
#pragma unroll
        for (int nt = 0; nt < 8; nt++) {
            int kcol = c * 64 + nt * 8 + qc;
            float b0 = sBias[kcol], b1 = sBias[kcol + 1];
#pragma unroll
            for (int mt = 0; mt < 2; mt++) {
                s[mt][nt][0] = s[mt][nt][0] * sc + b0;
                s[mt][nt][1] = s[mt][nt][1] * sc + b1;
                s[mt][nt][2] = s[mt][nt][2] * sc + b0;
                s[mt][nt][3] = s[mt][nt][3] * sc + b1;
            }
        }
#pragma unroll
        for (int mt = 0; mt < 2; mt++) {
            float rm0 = -1e30f, rm1 = -1e30f;
#pragma unroll
            for (int nt = 0; nt < 8; nt++) {
                rm0 = fmaxf(rm0, fmaxf(s[mt][nt][0], s[mt][nt][1]));
                rm1 = fmaxf(rm1, fmaxf(s[mt][nt][2], s[mt][nt][3]));
            }
#pragma unroll
            for (int o = 1; o <= 2; o <<= 1) {
                rm0 = fmaxf(rm0, __shfl_xor_sync(0xffffffffu, rm0, o));
                rm1 = fmaxf(rm1, __shfl_xor_sync(0xffffffffu, rm1, o));
            }
            float mn0 = fmaxf(mrow[mt][0], rm0), mn1 = fmaxf(mrow[mt][1], rm1);
            float sc0 = __expf(mrow[mt][0] - mn0), sc1 = __expf(mrow[mt][1] - mn1);
            mrow[mt][0] = mn0; mrow[mt][1] = mn1;
            float rs0 = 0.f, rs1 = 0.f;
#pragma unroll
            for (int nt = 0; nt < 8; nt++) {
                s[mt][nt][0] = __expf(s[mt][nt][0] - mn0);
                s[mt][nt][1] = __expf(s[mt][nt][1] - mn0);
                s[mt][nt][2] = __expf(s[mt][nt][2] - mn1);
                s[mt][nt][3] = __expf(s[mt][nt][3] - mn1);
                rs0 += s[mt][nt][0] + s[mt][nt][1];
                rs1 += s[mt][nt][2] + s[mt][nt][3];
            }
#pragma unroll
            for (int o = 1; o <= 2; o <<= 1) {
                rs0 += __shfl_xor_sync(0xffffffffu, rs0, o);
                rs1 += __shfl_xor_sync(0xffffffffu, rs1, o);
            }
            lrow[mt][0] = lrow[mt][0] * sc0 + rs0;
            lrow[mt][1] = lrow[mt][1] * sc1 + rs1;
#pragma unroll
            for (int d = 0; d < 4; d++) {
                O[mt][d][0] *= sc0; O[mt][d][1] *= sc0;
                O[mt][d][2] *= sc1; O[mt][d][3] *= sc1;
            }
        }
#pragma unroll
        for (int kt2 = 0; kt2 < 4; kt2++) {
            uint32_t pa[2][4];
#pragma unroll
            for (int mt = 0; mt < 2; mt++) {
                pa[mt][0] = packbf(s[mt][2 * kt2][0],     s[mt][2 * kt2][1]);
                pa[mt][1] = packbf(s[mt][2 * kt2][2],     s[mt][2 * kt2][3]);
                pa[mt][2] = packbf(s[mt][2 * kt2 + 1][0], s[mt][2 * kt2 + 1][1]);
                pa[mt][3] = packbf(s[mt][2 * kt2 + 1][2], s[mt][2 * kt2 + 1][3]);
            }
#pragma unroll
            for (int d = 0; d < 4; d++) {
                uint32_t vb[2];
                ldm2t(vb, &smV[c * 64 + kt2 * 16 + (lane & 15)][d * 8]);
                mma16816(O[0][d], pa[0], vb);
                mma16816(O[1][d], pa[1], vb);
            }
        }
    }

#pragma unroll
    for (int mt = 0; mt < 2; mt++) {
        float il0 = 1.f / lrow[mt][0], il1 = 1.f / lrow[mt][1];
        int r0 = w * 256 + warp * 32 + mt * 16 + qr;
#pragma unroll
        for (int d = 0; d < 4; d++) {
            int col = h * 32 + d * 8 + qc;
            *(bf162*)&g_AO[(size_t)r0 * 256 + col] =
                __floats2bfloat162_rn(O[mt][d][0] * il0, O[mt][d][1] * il0);
            *(bf162*)&g_AO[(size_t)(r0 + 8) * 256 + col] =
                __floats2bfloat162_rn(O[mt][d][2] * il1, O[mt][d][3] * il1);
        }
    }
}

// ---------------- launch ----------------
extern "C" void kernel_launch(void* const* d_in, const int* in_sizes, int n_in,
                              void* d_out, int out_size) {
    const float* x    = (const float*)d_in[0];
    const void*  mask = d_in[1];
    const float* pos  = (const float*)d_in[2];
    const float* Wemb = (const float*)d_in[3];
    const float* bemb = (const float*)d_in[4];
    const float* g1   = (const float*)d_in[5];
    const float* b1   = (const float*)d_in[6];
    const float* Wq   = (const float*)d_in[7];
    const float* bq   = (const float*)d_in[8];
    const float* Wk   = (const float*)d_in[9];
    const float* bk   = (const float*)d_in[10];
    const float* Wv   = (const float*)d_in[11];
    const float* bv   = (const float*)d_in[12];
    const float* Wo   = (const float*)d_in[13];
    const float* bo   = (const float*)d_in[14];
    const float* g2   = (const float*)d_in[15];
    const float* b2   = (const float*)d_in[16];
    const float* W1   = (const float*)d_in[17];
    const float* W2   = (const float*)d_in[18];
    const float* gam  = (const float*)d_in[19];
    const float* gmlp = (const float*)d_in[20];
    (void)in_sizes; (void)n_in;

    float* outx = (float*)d_out;
    int write_mask = (out_size >= 16777216 + 65536) ? 1 : 0;
    float* outmask = outx + 16777216;

    k_emb<<<256, 256>>>(pos, Wemb, bemb, g1, b1);
    k_wcvt<<<256, 256>>>(Wq, Wk, Wv, bq, bk, bv, Wo, W1, W2);
    k_maskprep<<<256, 256>>>(mask, outmask, write_mask);
    k_ln<<<8192, 256>>>(x, g1, b1, 1);
    dim3 gq(6, 512);
    k_gemm<<<gq, 256>>>(0, nullptr, nullptr, nullptr, nullptr);
    dim3 ga(256, 8);
    k_attn<<<ga, 256>>>();
    dim3 g2d(2, 512);
    k_gemm<<<g2d, 256>>>(1, bo, x, gam, outx);
    k_ln<<<8192, 256>>>(outx, g2, b2, 0);
    k_gemm<<<g2d, 256>>>(2, nullptr, nullptr, nullptr, nullptr);
    k_gemm<<<g2d, 256>>>(3, nullptr, nullptr, gmlp, outx);
}